// round 1
// baseline (speedup 1.0000x reference)
#include <cuda_runtime.h>

// Spalize: out[k][c][h][w] = img[c][h][w] * (mask[h][w] == k), k in [0,50)
// plus the mask itself appended (as float) if out_size covers it.
//
// HBM-write-bound: ~157MB of f32 output per call. Strategy: fully-coalesced
// float4 stores, one thread per 4-pixel quad, K split across blocks for
// wave balance.

#define KCH 50
#define CCH 3
#define KSPLIT 10
#define KCHUNK (KCH / KSPLIT)   // 5

// Mask may arrive as int32 (jax x64-disabled demotion) or int64. Detect at
// runtime: for little-endian int64 values in [0,50), every odd 32-bit word
// is zero. P(genuine int32 mask has 64 consecutive odd entries == 0) ~ 50^-64.
__device__ int g_mask_is64;

__global__ void detect_mask_width_kernel(const int* __restrict__ m) {
    if (blockIdx.x == 0 && threadIdx.x == 0) {
        int oddzero = 1;
        #pragma unroll 1
        for (int i = 0; i < 64; i++) {
            if (m[2 * i + 1] != 0) oddzero = 0;
        }
        g_mask_is64 = oddzero;
    }
}

__global__ void __launch_bounds__(256) spalize_kernel(
    const float* __restrict__ img,
    const int*   __restrict__ mask,
    float*       __restrict__ out,
    int nq,            // HW/4
    int nblocksQ)      // nq / blockDim
{
    const int qb = blockIdx.x % nblocksQ;
    const int ks = blockIdx.x / nblocksQ;          // which K-chunk
    const int q  = qb * blockDim.x + threadIdx.x;  // quad index
    if (q >= nq) return;

    const int is64 = g_mask_is64;

    // Load 4 mask labels for this quad
    int m0, m1, m2, m3;
    if (is64) {
        const int base = q * 8;   // 4 int64s = 8 int32 words; low word at even idx
        m0 = mask[base + 0];
        m1 = mask[base + 2];
        m2 = mask[base + 4];
        m3 = mask[base + 6];
    } else {
        const int4 mm = reinterpret_cast<const int4*>(mask)[q];
        m0 = mm.x; m1 = mm.y; m2 = mm.z; m3 = mm.w;
    }

    // Load img quad for each channel (stays in registers for all K iterations)
    const float4* img4 = reinterpret_cast<const float4*>(img);
    float4 ic0 = img4[0 * nq + q];
    float4 ic1 = img4[1 * nq + q];
    float4 ic2 = img4[2 * nq + q];

    float4* out4 = reinterpret_cast<float4*>(out);
    const int k0 = ks * KCHUNK;

    #pragma unroll
    for (int kk = 0; kk < KCHUNK; kk++) {
        const int k = k0 + kk;
        const float f0 = (m0 == k) ? 1.0f : 0.0f;
        const float f1 = (m1 == k) ? 1.0f : 0.0f;
        const float f2 = (m2 == k) ? 1.0f : 0.0f;
        const float f3 = (m3 == k) ? 1.0f : 0.0f;

        float4 v0, v1, v2;
        v0.x = ic0.x * f0; v0.y = ic0.y * f1; v0.z = ic0.z * f2; v0.w = ic0.w * f3;
        v1.x = ic1.x * f0; v1.y = ic1.y * f1; v1.z = ic1.z * f2; v1.w = ic1.w * f3;
        v2.x = ic2.x * f0; v2.y = ic2.y * f1; v2.z = ic2.z * f2; v2.w = ic2.w * f3;

        const long long obase = (long long)(k * CCH) * nq + q;
        out4[obase + 0LL * nq] = v0;
        out4[obase + 1LL * nq] = v1;
        out4[obase + 2LL * nq] = v2;
    }
}

// Append the mask (cast to float) after the spalized image block.
__global__ void mask_tail_kernel(const int* __restrict__ mask,
                                 float* __restrict__ out_tail,
                                 int HW)
{
    const int i = blockIdx.x * blockDim.x + threadIdx.x;
    if (i < HW) {
        const int is64 = g_mask_is64;
        const int v = is64 ? mask[2 * i] : mask[i];
        out_tail[i] = (float)v;
    }
}

extern "C" void kernel_launch(void* const* d_in, const int* in_sizes, int n_in,
                              void* d_out, int out_size)
{
    const float* img  = (const float*)d_in[0];
    const int*   mask = (const int*)d_in[1];
    float*       out  = (float*)d_out;

    const int HW = in_sizes[0] / CCH;       // 512*512 = 262144
    const int nq = HW >> 2;                 // 65536 quads

    detect_mask_width_kernel<<<1, 32>>>(mask);

    const int threads  = 256;
    const int nblocksQ = (nq + threads - 1) / threads;   // 256
    const int grid     = nblocksQ * KSPLIT;              // 2560 blocks
    spalize_kernel<<<grid, threads>>>(img, mask, out, nq, nblocksQ);

    const long long n_img = (long long)KCH * CCH * HW;   // 39,321,600
    if ((long long)out_size >= n_img + HW) {
        mask_tail_kernel<<<(HW + threads - 1) / threads, threads>>>(
            mask, out + n_img, HW);
    }
}

// round 2
// speedup vs baseline: 1.2342x; 1.2342x over previous
#include <cuda_runtime.h>

// Spalize: out[k][c][h][w] = img[c][h][w] * (mask[h][w] == k), k in [0,50),
// plus the mask appended (as float) if out_size covers it.
//
// Single fused kernel, HBM-write-bound (~157MB f32 out). Mask dtype
// (int32 vs int64, jax x64 demotion) detected inline per-warp via ballot
// over the first 64 odd 32-bit words (all zero <=> int64 little-endian
// values in [0,50)). False-positive prob ~ 50^-64.

#define KCH 50
#define CCH 3
#define KSPLIT 10
#define KCHUNK (KCH / KSPLIT)   // 5

__device__ __forceinline__ int detect_is64(const int* __restrict__ mask) {
    const int lane = threadIdx.x & 31;
    const int w1 = __ldg(&mask[2 * lane + 1]);
    const int w2 = __ldg(&mask[2 * (lane + 32) + 1]);
    const unsigned b = __ballot_sync(0xffffffffu, (w1 | w2) == 0);
    return b == 0xffffffffu;
}

__global__ void __launch_bounds__(256) spalize_fused_kernel(
    const float* __restrict__ img,
    const int*   __restrict__ mask,
    float*       __restrict__ out,
    int nq,            // HW/4
    int nblocksQ,      // ceil(nq/256)
    int nSpalBlocks)   // nblocksQ * KSPLIT; blocks beyond this do the mask tail
{
    const int is64 = detect_is64(mask);

    if (blockIdx.x >= nSpalBlocks) {
        // ---- mask tail: out[n_img + i] = (float)mask[i], 4 per thread ----
        const int tb = blockIdx.x - nSpalBlocks;
        const int q  = tb * blockDim.x + threadIdx.x;   // quad index
        if (q < nq) {
            int m0, m1, m2, m3;
            if (is64) {
                const int base = q * 8;
                m0 = mask[base + 0]; m1 = mask[base + 2];
                m2 = mask[base + 4]; m3 = mask[base + 6];
            } else {
                const int4 mm = reinterpret_cast<const int4*>(mask)[q];
                m0 = mm.x; m1 = mm.y; m2 = mm.z; m3 = mm.w;
            }
            float4 v = make_float4((float)m0, (float)m1, (float)m2, (float)m3);
            const long long n_img4 = (long long)KCH * CCH * nq;  // in float4 units
            reinterpret_cast<float4*>(out)[n_img4 + q] = v;
        }
        return;
    }

    // ---- spalize ----
    const int qb = blockIdx.x % nblocksQ;
    const int ks = blockIdx.x / nblocksQ;          // which K-chunk
    const int q  = qb * blockDim.x + threadIdx.x;  // quad index
    if (q >= nq) return;

    int m0, m1, m2, m3;
    if (is64) {
        const int base = q * 8;   // 4 int64s = 8 int32 words, low word first
        m0 = mask[base + 0]; m1 = mask[base + 2];
        m2 = mask[base + 4]; m3 = mask[base + 6];
    } else {
        const int4 mm = reinterpret_cast<const int4*>(mask)[q];
        m0 = mm.x; m1 = mm.y; m2 = mm.z; m3 = mm.w;
    }

    const float4* img4 = reinterpret_cast<const float4*>(img);
    float4 ic0 = img4[0 * nq + q];
    float4 ic1 = img4[1 * nq + q];
    float4 ic2 = img4[2 * nq + q];

    float4* out4 = reinterpret_cast<float4*>(out);
    const int k0 = ks * KCHUNK;

    #pragma unroll
    for (int kk = 0; kk < KCHUNK; kk++) {
        const int k = k0 + kk;
        const float f0 = (m0 == k) ? 1.0f : 0.0f;
        const float f1 = (m1 == k) ? 1.0f : 0.0f;
        const float f2 = (m2 == k) ? 1.0f : 0.0f;
        const float f3 = (m3 == k) ? 1.0f : 0.0f;

        float4 v0, v1, v2;
        v0.x = ic0.x * f0; v0.y = ic0.y * f1; v0.z = ic0.z * f2; v0.w = ic0.w * f3;
        v1.x = ic1.x * f0; v1.y = ic1.y * f1; v1.z = ic1.z * f2; v1.w = ic1.w * f3;
        v2.x = ic2.x * f0; v2.y = ic2.y * f1; v2.z = ic2.z * f2; v2.w = ic2.w * f3;

        const long long obase = (long long)(k * CCH) * nq + q;
        out4[obase + 0LL * nq] = v0;
        out4[obase + 1LL * nq] = v1;
        out4[obase + 2LL * nq] = v2;
    }
}

extern "C" void kernel_launch(void* const* d_in, const int* in_sizes, int n_in,
                              void* d_out, int out_size)
{
    const float* img  = (const float*)d_in[0];
    const int*   mask = (const int*)d_in[1];
    float*       out  = (float*)d_out;

    const int HW = in_sizes[0] / CCH;       // 512*512
    const int nq = HW >> 2;                 // 65536

    const int threads     = 256;
    const int nblocksQ    = (nq + threads - 1) / threads;   // 256
    const int nSpalBlocks = nblocksQ * KSPLIT;              // 2560

    const long long n_img = (long long)KCH * CCH * HW;
    const bool wantTail = ((long long)out_size >= n_img + HW);
    const int grid = nSpalBlocks + (wantTail ? nblocksQ : 0);

    spalize_fused_kernel<<<grid, threads>>>(img, mask, out, nq, nblocksQ, nSpalBlocks);
}